// round 14
// baseline (speedup 1.0000x reference)
#include <cuda_runtime.h>

#define N_ELEC 62
#define IN_CH  5
#define HID    32
#define N_CLS  3
#define GPB    16          // graphs per block = 8 pairs
#define NPAIRS 8
#define NTHR   512

typedef unsigned long long u64;

// A = S (symmetric), packed (hi_tf32, lo_tf32) u64, padded [64][66]
__device__ __align__(16) u64 g_Apk[64 * 66];

#define FMA2(acc, a, b) \
    asm("fma.rn.f32x2 %0, %1, %2, %0;" : "+l"(acc) : "l"(a), "l"(b))
#define PACK2(d, s) \
    asm("mov.b64 %0, {%1, %1};" : "=l"(d) : "f"(s))
#define UNPK2(lo, hi, v) \
    asm("mov.b64 {%0, %1}, %2;" : "=f"(lo), "=f"(hi) : "l"(v))

__device__ __forceinline__ unsigned f2tf32(float x) {
    unsigned r;
    asm("cvt.rna.tf32.f32 %0, %1;" : "=r"(r) : "f"(x));
    return r;
}
__device__ __forceinline__ u64 pack_hilo(float v) {
    unsigned hi = f2tf32(v);
    float lo_f = v - __uint_as_float(hi);
    unsigned lo = f2tf32(lo_f);
    return ((u64)lo << 32) | (u64)hi;
}
__device__ __forceinline__ u64 pack_ff(float lo, float hi) {
    u64 d;
    asm("mov.b64 %0, {%1, %2};" : "=l"(d) : "f"(lo), "f"(hi));
    return d;
}

#define MMA(d, a0,a1,a2,a3, b0,b1) \
    asm("mma.sync.aligned.m16n8k8.row.col.f32.tf32.tf32.f32 " \
        "{%0,%1,%2,%3}, {%4,%5,%6,%7}, {%8,%9}, {%0,%1,%2,%3};" \
        : "+f"(d[0]), "+f"(d[1]), "+f"(d[2]), "+f"(d[3]) \
        : "r"(a0), "r"(a1), "r"(a2), "r"(a3), "r"(b0), "r"(b1))

// ---------------------------------------------------------------------------
// Setup: 64 blocks; block i computes row i of S = M @ M (rows 62,63 -> 0),
// stored as packed tf32 (hi,lo) u64 with row stride 66 (cols 62..65 -> 0).
// ---------------------------------------------------------------------------
__global__ __launch_bounds__(128) void rgnn_setup_kernel(
    const float* __restrict__ adj_tril)
{
    cudaTriggerProgrammaticLaunchCompletion();

    const int tid = threadIdx.x;
    const int i   = blockIdx.x;

    if (i >= N_ELEC) {                   // zero pad rows 62, 63
        if (tid < 66) g_Apk[i * 66 + tid] = 0ull;
        return;
    }

    __shared__ float A[N_ELEC * 64];
    __shared__ float dinv[N_ELEC];
    __shared__ float tv[N_ELEC];

    for (int idx = tid; idx < N_ELEC * N_ELEC; idx += 128) {
        int r = idx / N_ELEC, c = idx % N_ELEC;
        int a = r > c ? r : c;
        int b = r > c ? c : r;
        A[r * 64 + c] = adj_tril[a * (a + 1) / 2 + b];
    }
    __syncthreads();

    if (tid < N_ELEC) {
        float d = 0.f;
        #pragma unroll 2
        for (int c = 0; c < N_ELEC; c++) d += fabsf(A[tid * 64 + c]);
        dinv[tid] = (d > 0.f) ? rsqrtf(d) : 0.f;
    }
    __syncthreads();

    if (tid < N_ELEC) {
        float dk = dinv[tid];
        tv[tid] = dinv[i] * dk * dk * A[i * 64 + tid];
    }
    __syncthreads();

    if (tid < 66) {
        const int j = tid;
        float s = 0.f;
        if (j < N_ELEC) {
            #pragma unroll 2
            for (int k = 0; k < N_ELEC; k++)
                s = fmaf(tv[k], A[k * 64 + j], s);
            s *= dinv[j];
        }
        g_Apk[i * 66 + j] = (j < N_ELEC) ? pack_hilo(s) : 0ull;
    }
}

// ---------------------------------------------------------------------------
// Main: phase A = tensor-core 3x-tf32 GEMM Y[64j][80n] = S[64][64] * X[64][80]
// (n = c*16 + g, so D-frag col pairs are (even,odd) graph pairs -> packed Ypk);
// phase B = R8's warp-per-(pair, j-half) relu/pool/fc, unchanged.
// ---------------------------------------------------------------------------
__global__ __launch_bounds__(NTHR) void rgnn_main_kernel(
    const float* __restrict__ x, const float* __restrict__ lin_w,
    const float* __restrict__ lin_b, const float* __restrict__ fc_w,
    const float* __restrict__ fc_b, float* __restrict__ out, int B)
{
    // dynamic smem: Apk [64][66]u64 @0 (33792B) | Bpk [64][100]u64 @33792 (51200B)
    // Ypk [40][66]u64 @0 aliases Apk after phase A.
    extern __shared__ __align__(16) unsigned char dsm[];
    u64* Apk = (u64*)dsm;
    u64* Bpk = (u64*)(dsm + 33792);
    u64* Ypk = (u64*)dsm;
    __shared__ float Wsh[HID][IN_CH];
    __shared__ float bsh[HID];
    __shared__ float Fsh[N_CLS][HID];
    __shared__ float fcb[N_CLS];
    __shared__ float red[NPAIRS][2][6];

    const int tid = threadIdx.x;
    const int g0  = blockIdx.x * GPB;

    // ---- prologue (independent of g_Apk; overlaps setup via PDL) ----
    if (tid < HID * IN_CH + HID + N_CLS * HID + N_CLS) {
        const int idx = tid;
        if (idx < 160)      ((float*)Wsh)[idx] = lin_w[idx];
        else if (idx < 192) bsh[idx - 160] = lin_b[idx - 160];
        else if (idx < 288) ((float*)Fsh)[idx - 192] = fc_w[idx - 192];
        else                fcb[idx - 288] = fc_b[idx - 288];
    }
    // X staging into Bpk[i][n], n = c*16 + g, packed tf32 (hi,lo)
    if (tid < 496) {
        const int g  = tid / 31;
        const int ii = tid - g * 31;
        const bool ok = (g0 + g) < B;
        const float* bx = x + ((size_t)(g0 + g) * N_ELEC) * IN_CH;
        #pragma unroll
        for (int rep = 0; rep < 2; rep++) {
            const int i = ii + rep * 31;
            const float* src = bx + i * IN_CH;
            #pragma unroll
            for (int c = 0; c < IN_CH; c++) {
                float v = ok ? src[c] : 0.f;
                Bpk[i * 100 + c * 16 + g] = pack_hilo(v);
            }
        }
    }
    if (tid < 160) {                      // zero k-pad rows 62,63 (n < 80)
        const int i = 62 + tid / 80;
        const int n = tid % 80;
        Bpk[i * 100 + n] = 0ull;
    }

    // ---- wait for setup's S, then stage A (float4 copy) ----
    cudaGridDependencySynchronize();
    {
        const float4* src = (const float4*)g_Apk;
        float4* dst = (float4*)Apk;
        for (int idx = tid; idx < 2112; idx += NTHR)
            dst[idx] = src[idx];
    }
    __syncthreads();

    // ---- phase A: mma.sync m16n8k8 tf32, 3x split ----
    const int l  = tid & 31;
    const int w  = tid >> 5;             // 0..15
    const int gr = l >> 2;               // lane group 0..7
    const int t  = l & 3;                // thread-in-group 0..3
    const int mt = w & 3;                // m-tile (j block of 16)
    const int q  = w >> 2;               // n-tile group: nt in {q, q+4, q+8}

    float acc[3][4];
    #pragma unroll
    for (int s = 0; s < 3; s++)
        #pragma unroll
        for (int r = 0; r < 4; r++) acc[s][r] = 0.f;

    {
        const unsigned ab = (unsigned)__cvta_generic_to_shared(Apk)
                            + ((mt * 16 + gr) * 66 + t) * 8;
        const unsigned bb = (unsigned)__cvta_generic_to_shared(Bpk)
                            + (t * 100 + q * 8 + gr) * 8;
        #pragma unroll
        for (int kt = 0; kt < 8; kt++) {
            unsigned ah0,al0, ah1,al1, ah2,al2, ah3,al3;
            const unsigned aa = ab + kt * 64;
            asm("ld.shared.v2.u32 {%0,%1}, [%2];"       : "=r"(ah0), "=r"(al0) : "r"(aa));
            asm("ld.shared.v2.u32 {%0,%1}, [%2+4224];"  : "=r"(ah1), "=r"(al1) : "r"(aa));
            asm("ld.shared.v2.u32 {%0,%1}, [%2+32];"    : "=r"(ah2), "=r"(al2) : "r"(aa));
            asm("ld.shared.v2.u32 {%0,%1}, [%2+4256];"  : "=r"(ah3), "=r"(al3) : "r"(aa));
            const unsigned bk = bb + kt * 6400;
            #pragma unroll
            for (int s = 0; s < 3; s++) {
                if (q + 4 * s < 10) {
                    unsigned bh0,bl0, bh1,bl1;
                    const unsigned ba = bk + s * 256;   // +32 n-cols
                    asm("ld.shared.v2.u32 {%0,%1}, [%2];"      : "=r"(bh0), "=r"(bl0) : "r"(ba));
                    asm("ld.shared.v2.u32 {%0,%1}, [%2+3200];" : "=r"(bh1), "=r"(bl1) : "r"(ba));
                    MMA(acc[s], ah0,ah1,ah2,ah3, bh0,bh1);
                    MMA(acc[s], ah0,ah1,ah2,ah3, bl0,bl1);
                    MMA(acc[s], al0,al1,al2,al3, bh0,bh1);
                }
            }
        }
    }
    __syncthreads();                      // all MMA reads of Apk retired

    // ---- epilogue: D frags -> packed Ypk[(p*5+c)*66 + j] ----
    {
        const int j0 = mt * 16 + gr;
        #pragma unroll
        for (int s = 0; s < 3; s++) {
            const int nt = q + 4 * s;
            if (nt < 10) {
                const int p = (nt & 1) * 4 + t;
                const int c = nt >> 1;
                const int row = (p * IN_CH + c) * 66;
                Ypk[row + j0]     = pack_ff(acc[s][0], acc[s][1]);
                Ypk[row + j0 + 8] = pack_ff(acc[s][2], acc[s][3]);
            }
        }
    }
    __syncthreads();                      // Ypk ready

    // ---- phase B: warp = (pair, j-half); lane = hidden unit o ----
    const int o  = l;
    const int pB = w >> 1;
    const int jh = w & 1;
    u64 wd0,wd1,wd2,wd3,wd4,bd;
    PACK2(wd0, Wsh[o][0]); PACK2(wd1, Wsh[o][1]); PACK2(wd2, Wsh[o][2]);
    PACK2(wd3, Wsh[o][3]); PACK2(wd4, Wsh[o][4]);
    PACK2(bd, bsh[o]);
    const float f0 = Fsh[0][o], f1 = Fsh[1][o], f2 = Fsh[2][o];

    {
        const unsigned yb = (unsigned)__cvta_generic_to_shared(Ypk)
                            + pB * 2640 + jh * 248;     // 31 j's * 8B
        float ph0 = 0.f, ph1 = 0.f;
        #pragma unroll 4
        for (int k = 0; k < 31; k++) {
            u64 y0,y1,y2,y3,y4;
            const unsigned a = yb + k * 8;
            asm("ld.shared.u64 %0, [%1];"       : "=l"(y0) : "r"(a));
            asm("ld.shared.u64 %0, [%1+528];"   : "=l"(y1) : "r"(a));
            asm("ld.shared.u64 %0, [%1+1056];"  : "=l"(y2) : "r"(a));
            asm("ld.shared.u64 %0, [%1+1584];"  : "=l"(y3) : "r"(a));
            asm("ld.shared.u64 %0, [%1+2112];"  : "=l"(y4) : "r"(a));
            u64 v = bd;
            FMA2(v, wd0, y0); FMA2(v, wd1, y1); FMA2(v, wd2, y2);
            FMA2(v, wd3, y3); FMA2(v, wd4, y4);
            float lo, hi; UNPK2(lo, hi, v);
            ph0 += fmaxf(lo, 0.f);               // graph 2*pB
            ph1 += fmaxf(hi, 0.f);               // graph 2*pB+1
        }
        float s0 = f0 * ph0, s1 = f1 * ph0, s2 = f2 * ph0;
        float t0 = f0 * ph1, t1 = f1 * ph1, t2 = f2 * ph1;
        #pragma unroll
        for (int off = 16; off > 0; off >>= 1) {
            s0 += __shfl_down_sync(0xffffffffu, s0, off);
            s1 += __shfl_down_sync(0xffffffffu, s1, off);
            s2 += __shfl_down_sync(0xffffffffu, s2, off);
            t0 += __shfl_down_sync(0xffffffffu, t0, off);
            t1 += __shfl_down_sync(0xffffffffu, t1, off);
            t2 += __shfl_down_sync(0xffffffffu, t2, off);
        }
        if (o == 0) {
            red[pB][jh][0] = s0; red[pB][jh][1] = s1; red[pB][jh][2] = s2;
            red[pB][jh][3] = t0; red[pB][jh][4] = t1; red[pB][jh][5] = t2;
        }
    }
    __syncthreads();

    if (tid < GPB * N_CLS) {
        const int gg = tid / N_CLS, c = tid % N_CLS;
        const int pp = gg >> 1, par = gg & 1;
        if (g0 + gg < B)
            out[(size_t)(g0 + gg) * N_CLS + c] =
                red[pp][0][par * 3 + c] + red[pp][1][par * 3 + c] + fcb[c];
    }
}

// ---------------------------------------------------------------------------
extern "C" void kernel_launch(void* const* d_in, const int* in_sizes, int n_in,
                              void* d_out, int out_size) {
    const float* x        = (const float*)d_in[0];
    const float* adj_tril = (const float*)d_in[1];
    const float* lin_w    = (const float*)d_in[2];
    const float* lin_b    = (const float*)d_in[3];
    const float* fc_w     = (const float*)d_in[4];
    const float* fc_b     = (const float*)d_in[5];
    // d_in[6] edge_index / d_in[7] batch_idx are structurally redundant.

    const int B = in_sizes[0] / (N_ELEC * IN_CH);
    const int SMEM_DYN = 33792 + 51200;   // Apk + Bpk

    cudaFuncSetAttribute(rgnn_main_kernel,
                         cudaFuncAttributeMaxDynamicSharedMemorySize, SMEM_DYN);

    rgnn_setup_kernel<<<64, 128>>>(adj_tril);

    const int grid = (B + GPB - 1) / GPB;
    cudaLaunchConfig_t cfg = {};
    cfg.gridDim  = dim3((unsigned)grid);
    cfg.blockDim = dim3(NTHR);
    cfg.dynamicSmemBytes = SMEM_DYN;
    cfg.stream = 0;
    cudaLaunchAttribute at[1];
    at[0].id = cudaLaunchAttributeProgrammaticStreamSerialization;
    at[0].val.programmaticStreamSerializationAllowed = 1;
    cfg.attrs = at;
    cfg.numAttrs = 1;
    cudaLaunchKernelEx(&cfg, rgnn_main_kernel,
                       x, lin_w, lin_b, fc_w, fc_b, (float*)d_out, B);
}

// round 15
// speedup vs baseline: 1.0014x; 1.0014x over previous
#include <cuda_runtime.h>

#define N_ELEC 62
#define IN_CH  5
#define HID    32
#define N_CLS  3
#define GPB    16          // graphs per block = 8 pairs
#define NPAIRS 8
#define NTHR   512

typedef unsigned long long u64;

// A = S (symmetric), packed (hi_tf32, lo_tf32) u64, padded [64][66]
__device__ __align__(16) u64 g_Apk[64 * 66];

#define FMA2(acc, a, b) \
    asm("fma.rn.f32x2 %0, %1, %2, %0;" : "+l"(acc) : "l"(a), "l"(b))
#define PACK2(d, s) \
    asm("mov.b64 %0, {%1, %1};" : "=l"(d) : "f"(s))
#define UNPK2(lo, hi, v) \
    asm("mov.b64 {%0, %1}, %2;" : "=f"(lo), "=f"(hi) : "l"(v))

__device__ __forceinline__ unsigned f2tf32(float x) {
    unsigned r;
    asm("cvt.rna.tf32.f32 %0, %1;" : "=r"(r) : "f"(x));
    return r;
}
__device__ __forceinline__ u64 pack_hilo(float v) {
    unsigned hi = f2tf32(v);
    float lo_f = v - __uint_as_float(hi);
    unsigned lo = f2tf32(lo_f);
    return ((u64)lo << 32) | (u64)hi;
}
__device__ __forceinline__ u64 pack_ff(float lo, float hi) {
    u64 d;
    asm("mov.b64 %0, {%1, %2};" : "=l"(d) : "f"(lo), "f"(hi));
    return d;
}

#define MMA(d, a0,a1,a2,a3, b0,b1) \
    asm("mma.sync.aligned.m16n8k8.row.col.f32.tf32.tf32.f32 " \
        "{%0,%1,%2,%3}, {%4,%5,%6,%7}, {%8,%9}, {%0,%1,%2,%3};" \
        : "+f"(d[0]), "+f"(d[1]), "+f"(d[2]), "+f"(d[3]) \
        : "r"(a0), "r"(a1), "r"(a2), "r"(a3), "r"(b0), "r"(b1))

// ---------------------------------------------------------------------------
// Setup: 64 blocks; block i computes row i of S = M @ M (rows 62,63 -> 0),
// stored as packed tf32 (hi,lo) u64 with row stride 66 (cols 62..65 -> 0).
// ---------------------------------------------------------------------------
__global__ __launch_bounds__(128) void rgnn_setup_kernel(
    const float* __restrict__ adj_tril)
{
    cudaTriggerProgrammaticLaunchCompletion();

    const int tid = threadIdx.x;
    const int i   = blockIdx.x;

    if (i >= N_ELEC) {                   // zero pad rows 62, 63
        if (tid < 66) g_Apk[i * 66 + tid] = 0ull;
        return;
    }

    __shared__ float A[N_ELEC * 64];
    __shared__ float dinv[N_ELEC];
    __shared__ float tv[N_ELEC];

    for (int idx = tid; idx < N_ELEC * N_ELEC; idx += 128) {
        int r = idx / N_ELEC, c = idx % N_ELEC;
        int a = r > c ? r : c;
        int b = r > c ? c : r;
        A[r * 64 + c] = adj_tril[a * (a + 1) / 2 + b];
    }
    __syncthreads();

    if (tid < N_ELEC) {
        float d = 0.f;
        #pragma unroll 2
        for (int c = 0; c < N_ELEC; c++) d += fabsf(A[tid * 64 + c]);
        dinv[tid] = (d > 0.f) ? rsqrtf(d) : 0.f;
    }
    __syncthreads();

    if (tid < N_ELEC) {
        float dk = dinv[tid];
        tv[tid] = dinv[i] * dk * dk * A[i * 64 + tid];
    }
    __syncthreads();

    if (tid < 66) {
        const int j = tid;
        float s = 0.f;
        if (j < N_ELEC) {
            #pragma unroll 2
            for (int k = 0; k < N_ELEC; k++)
                s = fmaf(tv[k], A[k * 64 + j], s);
            s *= dinv[j];
        }
        g_Apk[i * 66 + j] = (j < N_ELEC) ? pack_hilo(s) : 0ull;
    }
}

// ---------------------------------------------------------------------------
// Main: phase A = tensor-core 3x-tf32 GEMM Y[64j][80n] = S[64][64] * X[64][80]
// (n = c*16 + g, so D-frag col pairs are (even,odd) graph pairs -> packed Ypk);
// phase B = R8's warp-per-(pair, j-half) relu/pool/fc, unchanged.
// ---------------------------------------------------------------------------
__global__ __launch_bounds__(NTHR) void rgnn_main_kernel(
    const float* __restrict__ x, const float* __restrict__ lin_w,
    const float* __restrict__ lin_b, const float* __restrict__ fc_w,
    const float* __restrict__ fc_b, float* __restrict__ out, int B)
{
    // dynamic smem: Apk [64][66]u64 @0 (33792B) | Bpk [64][100]u64 @33792 (51200B)
    // Ypk [40][66]u64 @0 aliases Apk after phase A.
    extern __shared__ __align__(16) unsigned char dsm[];
    u64* Apk = (u64*)dsm;
    u64* Bpk = (u64*)(dsm + 33792);
    u64* Ypk = (u64*)dsm;
    __shared__ float Wsh[HID][IN_CH];
    __shared__ float bsh[HID];
    __shared__ float Fsh[N_CLS][HID];
    __shared__ float fcb[N_CLS];
    __shared__ float red[NPAIRS][2][6];

    const int tid = threadIdx.x;
    const int g0  = blockIdx.x * GPB;

    // ---- prologue (independent of g_Apk; overlaps setup via PDL) ----
    if (tid < HID * IN_CH + HID + N_CLS * HID + N_CLS) {
        const int idx = tid;
        if (idx < 160)      ((float*)Wsh)[idx] = lin_w[idx];
        else if (idx < 192) bsh[idx - 160] = lin_b[idx - 160];
        else if (idx < 288) ((float*)Fsh)[idx - 192] = fc_w[idx - 192];
        else                fcb[idx - 288] = fc_b[idx - 288];
    }
    // X staging into Bpk[i][n], n = c*16 + g, packed tf32 (hi,lo)
    if (tid < 496) {
        const int g  = tid / 31;
        const int ii = tid - g * 31;
        const bool ok = (g0 + g) < B;
        const float* bx = x + ((size_t)(g0 + g) * N_ELEC) * IN_CH;
        #pragma unroll
        for (int rep = 0; rep < 2; rep++) {
            const int i = ii + rep * 31;
            const float* src = bx + i * IN_CH;
            #pragma unroll
            for (int c = 0; c < IN_CH; c++) {
                float v = ok ? src[c] : 0.f;
                Bpk[i * 100 + c * 16 + g] = pack_hilo(v);
            }
        }
    }
    if (tid < 160) {                      // zero k-pad rows 62,63 (n < 80)
        const int i = 62 + tid / 80;
        const int n = tid % 80;
        Bpk[i * 100 + n] = 0ull;
    }

    // ---- wait for setup's S, then stage A (float4 copy) ----
    cudaGridDependencySynchronize();
    {
        const float4* src = (const float4*)g_Apk;
        float4* dst = (float4*)Apk;
        for (int idx = tid; idx < 2112; idx += NTHR)
            dst[idx] = src[idx];
    }
    __syncthreads();

    // ---- phase A: mma.sync m16n8k8 tf32, 3x split ----
    const int l  = tid & 31;
    const int w  = tid >> 5;             // 0..15
    const int gr = l >> 2;               // lane group 0..7
    const int t  = l & 3;                // thread-in-group 0..3
    const int mt = w & 3;                // m-tile (j block of 16)
    const int q  = w >> 2;               // n-tile group: nt in {q, q+4, q+8}

    float acc[3][4];
    #pragma unroll
    for (int s = 0; s < 3; s++)
        #pragma unroll
        for (int r = 0; r < 4; r++) acc[s][r] = 0.f;

    {
        const unsigned ab = (unsigned)__cvta_generic_to_shared(Apk)
                            + ((mt * 16 + gr) * 66 + t) * 8;
        const unsigned bb = (unsigned)__cvta_generic_to_shared(Bpk)
                            + (t * 100 + q * 8 + gr) * 8;
        #pragma unroll
        for (int kt = 0; kt < 8; kt++) {
            unsigned ah0,al0, ah1,al1, ah2,al2, ah3,al3;
            const unsigned aa = ab + kt * 64;
            asm("ld.shared.v2.u32 {%0,%1}, [%2];"       : "=r"(ah0), "=r"(al0) : "r"(aa));
            asm("ld.shared.v2.u32 {%0,%1}, [%2+4224];"  : "=r"(ah1), "=r"(al1) : "r"(aa));
            asm("ld.shared.v2.u32 {%0,%1}, [%2+32];"    : "=r"(ah2), "=r"(al2) : "r"(aa));
            asm("ld.shared.v2.u32 {%0,%1}, [%2+4256];"  : "=r"(ah3), "=r"(al3) : "r"(aa));
            const unsigned bk = bb + kt * 6400;
            #pragma unroll
            for (int s = 0; s < 3; s++) {
                if (q + 4 * s < 10) {
                    unsigned bh0,bl0, bh1,bl1;
                    const unsigned ba = bk + s * 256;   // +32 n-cols
                    asm("ld.shared.v2.u32 {%0,%1}, [%2];"      : "=r"(bh0), "=r"(bl0) : "r"(ba));
                    asm("ld.shared.v2.u32 {%0,%1}, [%2+3200];" : "=r"(bh1), "=r"(bl1) : "r"(ba));
                    MMA(acc[s], ah0,ah1,ah2,ah3, bh0,bh1);
                    MMA(acc[s], ah0,ah1,ah2,ah3, bl0,bl1);
                    MMA(acc[s], al0,al1,al2,al3, bh0,bh1);
                }
            }
        }
    }
    __syncthreads();                      // all MMA reads of Apk retired

    // ---- epilogue: D frags -> packed Ypk[(p*5+c)*66 + j] ----
    {
        const int j0 = mt * 16 + gr;
        #pragma unroll
        for (int s = 0; s < 3; s++) {
            const int nt = q + 4 * s;
            if (nt < 10) {
                const int p = (nt & 1) * 4 + t;
                const int c = nt >> 1;
                const int row = (p * IN_CH + c) * 66;
                Ypk[row + j0]     = pack_ff(acc[s][0], acc[s][1]);
                Ypk[row + j0 + 8] = pack_ff(acc[s][2], acc[s][3]);
            }
        }
    }
    __syncthreads();                      // Ypk ready

    // ---- phase B: warp = (pair, j-half); lane = hidden unit o ----
    const int o  = l;
    const int pB = w >> 1;
    const int jh = w & 1;
    u64 wd0,wd1,wd2,wd3,wd4,bd;
    PACK2(wd0, Wsh[o][0]); PACK2(wd1, Wsh[o][1]); PACK2(wd2, Wsh[o][2]);
    PACK2(wd3, Wsh[o][3]); PACK2(wd4, Wsh[o][4]);
    PACK2(bd, bsh[o]);
    const float f0 = Fsh[0][o], f1 = Fsh[1][o], f2 = Fsh[2][o];

    {
        const unsigned yb = (unsigned)__cvta_generic_to_shared(Ypk)
                            + pB * 2640 + jh * 248;     // 31 j's * 8B
        float ph0 = 0.f, ph1 = 0.f;
        #pragma unroll 4
        for (int k = 0; k < 31; k++) {
            u64 y0,y1,y2,y3,y4;
            const unsigned a = yb + k * 8;
            asm("ld.shared.u64 %0, [%1];"       : "=l"(y0) : "r"(a));
            asm("ld.shared.u64 %0, [%1+528];"   : "=l"(y1) : "r"(a));
            asm("ld.shared.u64 %0, [%1+1056];"  : "=l"(y2) : "r"(a));
            asm("ld.shared.u64 %0, [%1+1584];"  : "=l"(y3) : "r"(a));
            asm("ld.shared.u64 %0, [%1+2112];"  : "=l"(y4) : "r"(a));
            u64 v = bd;
            FMA2(v, wd0, y0); FMA2(v, wd1, y1); FMA2(v, wd2, y2);
            FMA2(v, wd3, y3); FMA2(v, wd4, y4);
            float lo, hi; UNPK2(lo, hi, v);
            ph0 += fmaxf(lo, 0.f);               // graph 2*pB
            ph1 += fmaxf(hi, 0.f);               // graph 2*pB+1
        }
        float s0 = f0 * ph0, s1 = f1 * ph0, s2 = f2 * ph0;
        float t0 = f0 * ph1, t1 = f1 * ph1, t2 = f2 * ph1;
        #pragma unroll
        for (int off = 16; off > 0; off >>= 1) {
            s0 += __shfl_down_sync(0xffffffffu, s0, off);
            s1 += __shfl_down_sync(0xffffffffu, s1, off);
            s2 += __shfl_down_sync(0xffffffffu, s2, off);
            t0 += __shfl_down_sync(0xffffffffu, t0, off);
            t1 += __shfl_down_sync(0xffffffffu, t1, off);
            t2 += __shfl_down_sync(0xffffffffu, t2, off);
        }
        if (o == 0) {
            red[pB][jh][0] = s0; red[pB][jh][1] = s1; red[pB][jh][2] = s2;
            red[pB][jh][3] = t0; red[pB][jh][4] = t1; red[pB][jh][5] = t2;
        }
    }
    __syncthreads();

    if (tid < GPB * N_CLS) {
        const int gg = tid / N_CLS, c = tid % N_CLS;
        const int pp = gg >> 1, par = gg & 1;
        if (g0 + gg < B)
            out[(size_t)(g0 + gg) * N_CLS + c] =
                red[pp][0][par * 3 + c] + red[pp][1][par * 3 + c] + fcb[c];
    }
}

// ---------------------------------------------------------------------------
extern "C" void kernel_launch(void* const* d_in, const int* in_sizes, int n_in,
                              void* d_out, int out_size) {
    const float* x        = (const float*)d_in[0];
    const float* adj_tril = (const float*)d_in[1];
    const float* lin_w    = (const float*)d_in[2];
    const float* lin_b    = (const float*)d_in[3];
    const float* fc_w     = (const float*)d_in[4];
    const float* fc_b     = (const float*)d_in[5];
    // d_in[6] edge_index / d_in[7] batch_idx are structurally redundant.

    const int B = in_sizes[0] / (N_ELEC * IN_CH);
    const int SMEM_DYN = 33792 + 51200;   // Apk + Bpk

    cudaFuncSetAttribute(rgnn_main_kernel,
                         cudaFuncAttributeMaxDynamicSharedMemorySize, SMEM_DYN);

    rgnn_setup_kernel<<<64, 128>>>(adj_tril);

    const int grid = (B + GPB - 1) / GPB;
    cudaLaunchConfig_t cfg = {};
    cfg.gridDim  = dim3((unsigned)grid);
    cfg.blockDim = dim3(NTHR);
    cfg.dynamicSmemBytes = SMEM_DYN;
    cfg.stream = 0;
    cudaLaunchAttribute at[1];
    at[0].id = cudaLaunchAttributeProgrammaticStreamSerialization;
    at[0].val.programmaticStreamSerializationAllowed = 1;
    cfg.attrs = at;
    cfg.numAttrs = 1;
    cudaLaunchKernelEx(&cfg, rgnn_main_kernel,
                       x, lin_w, lin_b, fc_w, fc_b, (float*)d_out, B);
}